// round 1
// baseline (speedup 1.0000x reference)
#include <cuda_runtime.h>

// Beamform_1649267442279 — GB300 sm_103a
//
// Structure of the reference (after de-sugaring):
//   Each channel s (4 channels, 10M complex samples each, stored interleaved
//   re/im in 20M floats) is cut into blocks of 20 complex samples
//   (40 floats). Block b, row r (0..3), col c (0..4):
//       re[r,c] = in_s[40*b + 10*r + 2*c]
//       im[r,c] = in_s[40*b + 10*r + 2*c + 1]
//   Output (2M blocks total, 10 floats per block, channel-major):
//       out[(s*Bc + b)*10 + c]     = sum_r br[r]*re[r,c] - bi[r]*im[r,c]
//       out[(s*Bc + b)*10 + 5 + c] = sum_r bi[r]*re[r,c] + br[r]*im[r,c]
//   with br[r] = bf[2r], bi[r] = bf[2r+1].
//
// Parallelization: thread = (block b, col j). 4x float2 loads at stride
// 10 floats keep each warp's footprint to 1KB per LDG (8 lines) so the
// L1tex wavefront pipe stays below the HBM roofline.

__global__ void __launch_bounds__(256)
beamform_kernel(const float* __restrict__ in0,
                const float* __restrict__ in1,
                const float* __restrict__ in2,
                const float* __restrict__ in3,
                const float* __restrict__ bf,
                float* __restrict__ out,
                int blocks_per_ch)
{
    const int g = blockIdx.x * blockDim.x + threadIdx.x;
    const int n_per_ch = blocks_per_ch * 5;
    if (g >= n_per_ch) return;

    const int ch = blockIdx.y;
    const float* __restrict__ in =
        (ch == 0) ? in0 : (ch == 1) ? in1 : (ch == 2) ? in2 : in3;

    const int b = g / 5;        // local block within channel
    const int j = g - b * 5;    // column 0..4

    // Beamforming weights: uniform address -> broadcast load, L1-resident.
    const float4 w0 = __ldg((const float4*)(bf));      // br0, bi0, br1, bi1
    const float4 w1 = __ldg((const float4*)(bf) + 1);  // br2, bi2, br3, bi3

    const float2* __restrict__ p =
        (const float2*)(in + (size_t)b * 40 + 2 * j);
    const float2 v0 = __ldg(p + 0);   // row 0: (re, im)
    const float2 v1 = __ldg(p + 5);   // row 1
    const float2 v2 = __ldg(p + 10);  // row 2
    const float2 v3 = __ldg(p + 15);  // row 3

    float re = w0.x * v0.x - w0.y * v0.y;
    float im = w0.y * v0.x + w0.x * v0.y;
    re += w0.z * v1.x - w0.w * v1.y;
    im += w0.w * v1.x + w0.z * v1.y;
    re += w1.x * v2.x - w1.y * v2.y;
    im += w1.y * v2.x + w1.x * v2.y;
    re += w1.z * v3.x - w1.w * v3.y;
    im += w1.w * v3.x + w1.z * v3.y;

    const size_t ob = ((size_t)ch * blocks_per_ch + (size_t)b) * 10;
    out[ob + j]     = re;
    out[ob + 5 + j] = im;
}

extern "C" void kernel_launch(void* const* d_in, const int* in_sizes, int n_in,
                              void* d_out, int out_size)
{
    const float* in0 = (const float*)d_in[0];
    const float* in1 = (const float*)d_in[1];
    const float* in2 = (const float*)d_in[2];
    const float* in3 = (const float*)d_in[3];
    const float* bf  = (const float*)d_in[4];
    float* out = (float*)d_out;

    const int N  = in_sizes[0];      // 20,000,000 interleaved floats / channel
    const int Bc = N / 40;           // 500,000 blocks per channel

    const int threads = 256;
    const int n_per_ch = Bc * 5;     // 2.5M threads per channel
    dim3 grid((n_per_ch + threads - 1) / threads, 4);

    beamform_kernel<<<grid, threads>>>(in0, in1, in2, in3, bf, out, Bc);
}